// round 3
// baseline (speedup 1.0000x reference)
#include <cuda_runtime.h>
#include <math.h>

#define NL   3
#define NB   64
#define NSEQ 48
#define DM   256
#define NH   8
#define HDM  32
#define FFD  1024
#define INP  17

// ---------------- static device scratch (no runtime allocation) ----------------
__device__ float g_wqT[NL][DM][DM];     // wqT[l][j][r] = w_qkv[l][r][j],      r in [0,256)
__device__ float g_wkT[NL][DM][DM];     //                                    r in [256,512)
__device__ float g_wvT[NL][DM][DM];     //                                    r in [512,768)
__device__ float g_woT[NL][DM][DM];     // woT[l][j][r] = w_o[l][r][j]
__device__ float g_wff1T[NL][DM][FFD];  // [j][r], r<FFD
__device__ float g_wff2T[NL][FFD][DM];  // [j][r], j<FFD, r<DM
__device__ float g_winT[INP][DM];       // [j][r]
__device__ float g_wp1T[DM][128];       // [j][r]
__device__ float g_kc[NL][NB][NSEQ][DM];
__device__ float g_vc[NL][NB][NSEQ][DM];

// ---------------- prep: transpose weights for coalesced GEMV loads ----------------
__global__ void prep_kernel(const float* __restrict__ w_qkv, const float* __restrict__ w_o,
                            const float* __restrict__ w_ff1, const float* __restrict__ w_ff2,
                            const float* __restrict__ w_in,  const float* __restrict__ w_p1)
{
    int tid = blockIdx.x * blockDim.x + threadIdx.x;
    int nth = gridDim.x * blockDim.x;

    for (int i = tid; i < NL*3*DM*DM; i += nth) {
        int l = i / (3*DM*DM); int rem = i - l*3*DM*DM; int r = rem / DM; int j = rem - r*DM;
        float v = w_qkv[i];
        int sel = r >> 8; int rr = r & 255;
        if (sel == 0)      g_wqT[l][j][rr] = v;
        else if (sel == 1) g_wkT[l][j][rr] = v;
        else               g_wvT[l][j][rr] = v;
    }
    for (int i = tid; i < NL*DM*DM; i += nth) {
        int l = i / (DM*DM); int rem = i - l*DM*DM; int r = rem / DM; int j = rem - r*DM;
        g_woT[l][j][r] = w_o[i];
    }
    for (int i = tid; i < NL*FFD*DM; i += nth) {
        int l = i / (FFD*DM); int rem = i - l*FFD*DM; int r = rem / DM; int j = rem - r*DM;
        g_wff1T[l][j][r] = w_ff1[i];
    }
    for (int i = tid; i < NL*DM*FFD; i += nth) {
        int l = i / (DM*FFD); int rem = i - l*DM*FFD; int r = rem / FFD; int j = rem - r*FFD;
        g_wff2T[l][j][r] = w_ff2[i];
    }
    for (int i = tid; i < DM*INP; i += nth) {
        int r = i / INP; int j = i - r*INP;
        g_winT[j][r] = w_in[i];
    }
    for (int i = tid; i < 128*DM; i += nth) {
        int r = i / DM; int j = i - r*DM;
        g_wp1T[j][r] = w_p1[i];
    }
}

// ---------------- GEMV: threads own 4 consecutive rows; j-dimension split so all
// 256 threads are busy for small O. Writes float4 partials to partbuf (S*O floats). ----
template<int O, int I>
__device__ __forceinline__ void gemv_part(const float* __restrict__ wT,
                                          const float* __restrict__ xsrc,
                                          float* __restrict__ partbuf, int t)
{
    constexpr int G  = O / 4;        // float4 row-groups
    constexpr int S  = 256 / G;      // j-splits across threads
    constexpr int JC = I / S;        // j-range per split (multiple of 4)
    const int g = t % G;
    const int s = t / G;
    const float4* __restrict__ w4 = reinterpret_cast<const float4*>(wT);
    const float4* __restrict__ x4 = reinterpret_cast<const float4*>(xsrc);
    float ax = 0.f, ay = 0.f, az = 0.f, aw = 0.f;
    const int jb = s * JC;
    #pragma unroll 4
    for (int u = 0; u < JC/4; ++u) {
        float4 xv = x4[(jb >> 2) + u];
        const float4* wp = w4 + (size_t)(jb + 4*u) * G + g;
        float4 w0 = wp[0];
        float4 w1 = wp[G];
        float4 w2 = wp[2*G];
        float4 w3 = wp[3*G];
        ax = fmaf(w0.x, xv.x, ax); ay = fmaf(w0.y, xv.x, ay); az = fmaf(w0.z, xv.x, az); aw = fmaf(w0.w, xv.x, aw);
        ax = fmaf(w1.x, xv.y, ax); ay = fmaf(w1.y, xv.y, ay); az = fmaf(w1.z, xv.y, az); aw = fmaf(w1.w, xv.y, aw);
        ax = fmaf(w2.x, xv.z, ax); ay = fmaf(w2.y, xv.z, ay); az = fmaf(w2.z, xv.z, az); aw = fmaf(w2.w, xv.z, aw);
        ax = fmaf(w3.x, xv.w, ax); ay = fmaf(w3.y, xv.w, ay); az = fmaf(w3.z, xv.w, az); aw = fmaf(w3.w, xv.w, aw);
    }
    float4 r; r.x = ax; r.y = ay; r.z = az; r.w = aw;
    reinterpret_cast<float4*>(partbuf)[s*G + g] = r;
}

__device__ __forceinline__ float gelu_exact(float x) {
    return 0.5f * x * (1.0f + erff(x * 0.70710678118654746f));
}

// sum-reduce two values over the whole block (256 threads, 8 warps)
__device__ __forceinline__ void block_reduce2(float& a, float& b, float* red, int lane, int warp)
{
    #pragma unroll
    for (int m = 16; m; m >>= 1) {
        a += __shfl_xor_sync(0xffffffffu, a, m);
        b += __shfl_xor_sync(0xffffffffu, b, m);
    }
    if (lane == 0) { red[warp] = a; red[8 + warp] = b; }
    __syncthreads();
    if (warp == 0) {
        float aa = (lane < 8) ? red[lane]     : 0.f;
        float bb = (lane < 8) ? red[8 + lane] : 0.f;
        #pragma unroll
        for (int m = 4; m; m >>= 1) {
            aa += __shfl_xor_sync(0xffffffffu, aa, m);
            bb += __shfl_xor_sync(0xffffffffu, bb, m);
        }
        if (lane == 0) { red[0] = aa; red[8] = bb; }
    }
    __syncthreads();
    a = red[0]; b = red[8];
}

// ---------------- main: one block per batch element, full autoregressive loop ----------------
__global__ __launch_bounds__(256, 1) void hedge_kernel(
    const float* __restrict__ feat,
    const float* __restrict__ b_in,
    const float* __restrict__ b_qkv,
    const float* __restrict__ b_o,
    const float* __restrict__ ln1_g, const float* __restrict__ ln1_b,
    const float* __restrict__ b_ff1, const float* __restrict__ b_ff2,
    const float* __restrict__ ln2_g, const float* __restrict__ ln2_b,
    const float* __restrict__ b_p1,
    const float* __restrict__ w_p2,  const float* __restrict__ b_p2,
    float* __restrict__ out)
{
    const int b    = blockIdx.x;
    const int t    = threadIdx.x;
    const int lane = t & 31;
    const int warp = t >> 5;

    __shared__ __align__(16) float xs[DM];
    __shared__ __align__(16) float qs[DM];
    __shared__ __align__(16) float ctx[DM];
    __shared__ __align__(16) float ffs[FFD];
    __shared__ __align__(16) float part[1024];
    __shared__ float sc[NH][NSEQ];
    __shared__ float h1[128];
    __shared__ float xin[INP + 3];
    __shared__ float red[16];
    __shared__ float sdelta;

    // sinusoidal PE factor for this dim: div = exp((t & ~1) * (-ln(10000)/256))
    const float div_t = expf((float)(t & ~1) * (-9.210340371976184f / 256.f));
    const float scale = 0.17677669529663687f;  // 1/sqrt(32)

    if (t == 0) sdelta = 0.f;
    __syncthreads();

    for (int k = 0; k < NSEQ; ++k) {
        // ---- build token input [features(16), prev_delta] ----
        if (t < 16)       xin[t]  = feat[((b*NSEQ) + k)*16 + t];
        else if (t == 16) xin[16] = sdelta;
        __syncthreads();

        // ---- input projection + positional encoding ----
        {
            float acc = b_in[t];
            #pragma unroll
            for (int j = 0; j < INP; ++j) acc = fmaf(g_winT[j][t], xin[j], acc);
            float ang = (float)k * div_t;
            acc += (t & 1) ? cosf(ang) : sinf(ang);
            xs[t] = acc;
        }
        __syncthreads();

        for (int l = 0; l < NL; ++l) {
            const float* bq = b_qkv + l*3*DM;

            // ---- Q ----
            gemv_part<DM, DM>(&g_wqT[l][0][0], xs, part, t);
            __syncthreads();
            qs[t] = part[t] + part[256+t] + part[512+t] + part[768+t] + bq[t];
            __syncthreads();
            // ---- K -> cache ----
            gemv_part<DM, DM>(&g_wkT[l][0][0], xs, part, t);
            __syncthreads();
            g_kc[l][b][k][t] = part[t] + part[256+t] + part[512+t] + part[768+t] + bq[DM + t];
            __syncthreads();
            // ---- V -> cache ----
            gemv_part<DM, DM>(&g_wvT[l][0][0], xs, part, t);
            __syncthreads();
            g_vc[l][b][k][t] = part[t] + part[256+t] + part[512+t] + part[768+t] + bq[2*DM + t];
            __syncthreads();

            // ---- attention: warp h owns head h (32 lanes = 32 head dims) ----
            {
                const int off = warp*HDM + lane;
                const float ql = qs[off];
                const float* kcp = &g_kc[l][b][0][0];
                const float* vcp = &g_vc[l][b][0][0];
                int p = 0;
                for (; p + 1 <= k; p += 2) {           // two interleaved reductions
                    float s0 = ql * kcp[p*DM + off];
                    float s1 = ql * kcp[(p+1)*DM + off];
                    #pragma unroll
                    for (int m = 16; m; m >>= 1) {
                        s0 += __shfl_xor_sync(0xffffffffu, s0, m);
                        s1 += __shfl_xor_sync(0xffffffffu, s1, m);
                    }
                    if (lane == 0) { sc[warp][p] = s0*scale; sc[warp][p+1] = s1*scale; }
                }
                if (p <= k) {
                    float s0 = ql * kcp[p*DM + off];
                    #pragma unroll
                    for (int m = 16; m; m >>= 1) s0 += __shfl_xor_sync(0xffffffffu, s0, m);
                    if (lane == 0) sc[warp][p] = s0*scale;
                }
                __syncwarp();
                // softmax over positions [0, k]
                float v0 = (lane      <= k) ? sc[warp][lane]      : -3.0e38f;
                float v1 = (lane + 32 <= k) ? sc[warp][lane + 32] : -3.0e38f;
                float mx = fmaxf(v0, v1);
                #pragma unroll
                for (int m = 16; m; m >>= 1) mx = fmaxf(mx, __shfl_xor_sync(0xffffffffu, mx, m));
                float e0 = (lane      <= k) ? expf(v0 - mx) : 0.f;
                float e1 = (lane + 32 <= k) ? expf(v1 - mx) : 0.f;
                float sum = e0 + e1;
                #pragma unroll
                for (int m = 16; m; m >>= 1) sum += __shfl_xor_sync(0xffffffffu, sum, m);
                float inv = 1.f / sum;
                if (lane      <= k) sc[warp][lane]      = e0 * inv;
                if (lane + 32 <= k) sc[warp][lane + 32] = e1 * inv;
                __syncwarp();
                float acc = 0.f;
                for (int pp = 0; pp <= k; ++pp)
                    acc = fmaf(sc[warp][pp], vcp[pp*DM + off], acc);
                ctx[off] = acc;
            }
            __syncthreads();

            // ---- O projection + residual + LN1 ----
            gemv_part<DM, DM>(&g_woT[l][0][0], ctx, part, t);
            __syncthreads();
            {
                float v = xs[t] + b_o[l*DM + t] + part[t] + part[256+t] + part[512+t] + part[768+t];
                float s1 = v, s2 = v*v;
                block_reduce2(s1, s2, red, lane, warp);
                float m   = s1 * (1.f/256.f);
                float var = s2 * (1.f/256.f) - m*m;
                xs[t] = (v - m) * rsqrtf(var + 1e-5f) * ln1_g[l*DM + t] + ln1_b[l*DM + t];
            }
            __syncthreads();

            // ---- FF1 + exact GELU ----
            gemv_part<FFD, DM>(&g_wff1T[l][0][0], xs, part, t);
            __syncthreads();
            {
                const float* bf = b_ff1 + l*FFD;
                #pragma unroll
                for (int r = t; r < FFD; r += 256) ffs[r] = gelu_exact(part[r] + bf[r]);
            }
            __syncthreads();

            // ---- FF2 + residual + LN2 ----
            gemv_part<DM, FFD>(&g_wff2T[l][0][0], ffs, part, t);
            __syncthreads();
            {
                float v = xs[t] + b_ff2[l*DM + t] + part[t] + part[256+t] + part[512+t] + part[768+t];
                float s1 = v, s2 = v*v;
                block_reduce2(s1, s2, red, lane, warp);
                float m   = s1 * (1.f/256.f);
                float var = s2 * (1.f/256.f) - m*m;
                xs[t] = (v - m) * rsqrtf(var + 1e-5f) * ln2_g[l*DM + t] + ln2_b[l*DM + t];
            }
            __syncthreads();
        }

        // ---- head: p1 (gelu) then p2 (scalar) ----
        gemv_part<128, DM>(&g_wp1T[0][0], xs, part, t);
        __syncthreads();
        if (t < 128) {
            float acc = b_p1[t];
            #pragma unroll
            for (int s = 0; s < 8; ++s) acc += part[s*128 + t];
            h1[t] = gelu_exact(acc);
        }
        __syncthreads();
        if (warp == 0) {
            float v = w_p2[lane]      * h1[lane]
                    + w_p2[lane + 32] * h1[lane + 32]
                    + w_p2[lane + 64] * h1[lane + 64]
                    + w_p2[lane + 96] * h1[lane + 96];
            #pragma unroll
            for (int m = 16; m; m >>= 1) v += __shfl_xor_sync(0xffffffffu, v, m);
            if (lane == 0) {
                float d = v + b_p2[0];
                out[b*NSEQ + k] = d;
                sdelta = d;
            }
        }
        __syncthreads();
    }
}

extern "C" void kernel_launch(void* const* d_in, const int* in_sizes, int n_in,
                              void* d_out, int out_size)
{
    const float* feat  = (const float*)d_in[0];
    const float* w_in  = (const float*)d_in[1];
    const float* b_in  = (const float*)d_in[2];
    const float* w_qkv = (const float*)d_in[3];
    const float* b_qkv = (const float*)d_in[4];
    const float* w_o   = (const float*)d_in[5];
    const float* b_o   = (const float*)d_in[6];
    const float* ln1_g = (const float*)d_in[7];
    const float* ln1_b = (const float*)d_in[8];
    const float* w_ff1 = (const float*)d_in[9];
    const float* b_ff1 = (const float*)d_in[10];
    const float* w_ff2 = (const float*)d_in[11];
    const float* b_ff2 = (const float*)d_in[12];
    const float* ln2_g = (const float*)d_in[13];
    const float* ln2_b = (const float*)d_in[14];
    const float* w_p1  = (const float*)d_in[15];
    const float* b_p1  = (const float*)d_in[16];
    const float* w_p2  = (const float*)d_in[17];
    const float* b_p2  = (const float*)d_in[18];
    float* out = (float*)d_out;

    prep_kernel<<<512, 256>>>(w_qkv, w_o, w_ff1, w_ff2, w_in, w_p1);
    hedge_kernel<<<NB, 256>>>(feat, b_in, b_qkv, b_o, ln1_g, ln1_b,
                              b_ff1, b_ff2, ln2_g, ln2_b, b_p1, w_p2, b_p2, out);
}